// round 1
// baseline (speedup 1.0000x reference)
#include <cuda_runtime.h>
#include <cuda_bf16.h>
#include <cstddef>

#define N_ROWS 500000
#define D_IN   128
#define R_DIM  256
#define D_OUT  64
#define U_DIM  10000
#define EPS    1e-8f

// ---------------- device scratch (statics are the allowed scratch path) ----
__device__ float g_Wvar0[D_IN * R_DIM];          // exp(W_lv0)            128x256
__device__ float g_Wvar1[R_DIM * D_OUT];         // exp(W_lv1)            256x64
__device__ float g_A1[R_DIM * D_OUT];            // Wmu1^2 + Wvar1        256x64
__device__ float g_m0[(size_t)N_ROWS * R_DIM];   // layer0 mean           512 MB
__device__ float g_v0[(size_t)N_ROWS * R_DIM];   // layer0 var            512 MB
__device__ float g_sum_inv[U_DIM * D_OUT];       // sum of 1/v per uid
__device__ float g_sum_minv[U_DIM * D_OUT];      // sum of m/v per uid

// ---------------- prep: exp weights, derived weights, zero accumulators ---
__global__ __launch_bounds__(256) void prep_kernel(const float* __restrict__ Wlv0,
                                                   const float* __restrict__ Wmu1,
                                                   const float* __restrict__ Wlv1) {
    int id = blockIdx.x * 256 + threadIdx.x;
    if (id < D_IN * R_DIM) g_Wvar0[id] = expf(Wlv0[id]);
    if (id < R_DIM * D_OUT) {
        float e = expf(Wlv1[id]);
        g_Wvar1[id] = e;
        float w = Wmu1[id];
        g_A1[id] = w * w + e;
    }
    if (id < U_DIM * D_OUT) {
        g_sum_inv[id]  = 0.f;
        g_sum_minv[id] = 0.f;
    }
}

// ---------------- layer 0: m0 = relu-gated X@Wmu0, v0 = gated X^2@Wvar0 ----
// Tile: 64 rows x 64 cols per block, K=128 in 4 chunks of 32.
// 256 threads as 16x16, each owns a 4x4 fragment of M and of V.
__global__ __launch_bounds__(256) void layer0_kernel(const float* __restrict__ X,
                                                     const float* __restrict__ Wmu0) {
    const int rowBase = blockIdx.x * 64;
    const int colBase = blockIdx.y * 64;
    const int t  = threadIdx.x;
    const int tx = t & 15;   // col group
    const int ty = t >> 4;   // row group

    __shared__ float XsT[32][68];   // transposed X chunk: [k][row], pad to keep 16B rows
    __shared__ float Wm[32][64];
    __shared__ float Wv[32][64];

    float accM[4][4] = {};
    float accV[4][4] = {};

    for (int k0 = 0; k0 < D_IN; k0 += 32) {
        // load X tile (64 rows x 32 cols), store transposed
        #pragma unroll
        for (int rep = 0; rep < 2; rep++) {
            int idx  = t + rep * 256;
            int row  = idx >> 3;          // 0..63
            int c4   = idx & 7;           // 0..7
            int grow = rowBase + row;
            float4 val = make_float4(0.f, 0.f, 0.f, 0.f);
            if (grow < N_ROWS)
                val = *(const float4*)&X[(size_t)grow * D_IN + k0 + c4 * 4];
            XsT[c4 * 4 + 0][row] = val.x;
            XsT[c4 * 4 + 1][row] = val.y;
            XsT[c4 * 4 + 2][row] = val.z;
            XsT[c4 * 4 + 3][row] = val.w;
        }
        // load weight tiles (32 rows x 64 cols), row-major [D_IN][R]
        #pragma unroll
        for (int rep = 0; rep < 2; rep++) {
            int idx = t + rep * 256;
            int row = idx >> 4;           // 0..31
            int c4  = idx & 15;           // 0..15
            size_t goff = (size_t)(k0 + row) * R_DIM + colBase + c4 * 4;
            *(float4*)&Wm[row][c4 * 4] = *(const float4*)&Wmu0[goff];
            *(float4*)&Wv[row][c4 * 4] = *(const float4*)&g_Wvar0[goff];
        }
        __syncthreads();

        #pragma unroll
        for (int kk = 0; kk < 32; kk++) {
            float4 xv = *(float4*)&XsT[kk][ty * 4];
            float4 wm = *(float4*)&Wm[kk][tx * 4];
            float4 wv = *(float4*)&Wv[kk][tx * 4];
            float x[4]  = {xv.x, xv.y, xv.z, xv.w};
            float wmv[4] = {wm.x, wm.y, wm.z, wm.w};
            float wvv[4] = {wv.x, wv.y, wv.z, wv.w};
            #pragma unroll
            for (int i = 0; i < 4; i++) {
                float xx = x[i] * x[i];
                #pragma unroll
                for (int j = 0; j < 4; j++) {
                    accM[i][j] += x[i] * wmv[j];
                    accV[i][j] += xx   * wvv[j];
                }
            }
        }
        __syncthreads();
    }

    // relu gate + store
    #pragma unroll
    for (int i = 0; i < 4; i++) {
        int grow = rowBase + ty * 4 + i;
        if (grow >= N_ROWS) break;
        float4 mo, vo;
        float* mp = &mo.x;
        float* vp = &vo.x;
        #pragma unroll
        for (int j = 0; j < 4; j++) {
            float m = accM[i][j];
            bool g = (m > 0.f);
            mp[j] = g ? m : 0.f;
            vp[j] = g ? accV[i][j] : 0.f;
        }
        size_t off = (size_t)grow * R_DIM + colBase + tx * 4;
        *(float4*)&g_m0[off] = mo;
        *(float4*)&g_v0[off] = vo;
    }
}

// ---------------- layer 1 + precision-weighted aggregation -----------------
// Tile: 64 rows x 64 cols (= full D_OUT), K=256 in 8 chunks of 32.
__global__ __launch_bounds__(256) void layer1_agg_kernel(const int* __restrict__ X_idx,
                                                         const float* __restrict__ Wmu1) {
    const int rowBase = blockIdx.x * 64;
    const int t  = threadIdx.x;
    const int tx = t & 15;
    const int ty = t >> 4;

    __shared__ float MsT[32][68];
    __shared__ float VsT[32][68];
    __shared__ float Wm1[32][64];
    __shared__ float A1s[32][64];
    __shared__ float Wv1[32][64];

    float accM[4][4] = {};
    float accV[4][4] = {};

    for (int k0 = 0; k0 < R_DIM; k0 += 32) {
        #pragma unroll
        for (int rep = 0; rep < 2; rep++) {
            int idx  = t + rep * 256;
            int row  = idx >> 3;
            int c4   = idx & 7;
            int grow = rowBase + row;
            float4 mv = make_float4(0.f, 0.f, 0.f, 0.f);
            float4 vv = make_float4(0.f, 0.f, 0.f, 0.f);
            if (grow < N_ROWS) {
                size_t off = (size_t)grow * R_DIM + k0 + c4 * 4;
                mv = *(const float4*)&g_m0[off];
                vv = *(const float4*)&g_v0[off];
            }
            #pragma unroll
            for (int j = 0; j < 4; j++) {
                MsT[c4 * 4 + j][row] = (&mv.x)[j];
                VsT[c4 * 4 + j][row] = (&vv.x)[j];
            }
        }
        #pragma unroll
        for (int rep = 0; rep < 2; rep++) {
            int idx = t + rep * 256;
            int row = idx >> 4;           // 0..31
            int c4  = idx & 15;           // 0..15
            size_t goff = (size_t)(k0 + row) * D_OUT + c4 * 4;
            *(float4*)&Wm1[row][c4 * 4] = *(const float4*)&Wmu1[goff];
            *(float4*)&A1s[row][c4 * 4] = *(const float4*)&g_A1[goff];
            *(float4*)&Wv1[row][c4 * 4] = *(const float4*)&g_Wvar1[goff];
        }
        __syncthreads();

        #pragma unroll
        for (int kk = 0; kk < 32; kk++) {
            float4 mv = *(float4*)&MsT[kk][ty * 4];
            float4 vv = *(float4*)&VsT[kk][ty * 4];
            float4 wm = *(float4*)&Wm1[kk][tx * 4];
            float4 aa = *(float4*)&A1s[kk][tx * 4];
            float4 wv = *(float4*)&Wv1[kk][tx * 4];
            float m[4] = {mv.x, mv.y, mv.z, mv.w};
            float v[4] = {vv.x, vv.y, vv.z, vv.w};
            float wmj[4] = {wm.x, wm.y, wm.z, wm.w};
            float aaj[4] = {aa.x, aa.y, aa.z, aa.w};
            float wvj[4] = {wv.x, wv.y, wv.z, wv.w};
            #pragma unroll
            for (int i = 0; i < 4; i++) {
                float mm = m[i] * m[i];
                #pragma unroll
                for (int j = 0; j < 4; j++) {
                    accM[i][j] += m[i] * wmj[j];
                    accV[i][j] += v[i] * aaj[j];
                    accV[i][j] += mm   * wvj[j];
                }
            }
        }
        __syncthreads();
    }

    // epilogue: inv-variance weighting + segment atomics.
    // rows owned by this thread are 4 consecutive global rows; X_idx is sorted,
    // so merge equal-uid rows before hitting global atomics.
    float aInv[4]  = {0.f, 0.f, 0.f, 0.f};
    float aMinv[4] = {0.f, 0.f, 0.f, 0.f};
    int curUid = -1;
    #pragma unroll
    for (int i = 0; i < 4; i++) {
        int grow = rowBase + ty * 4 + i;
        if (grow >= N_ROWS) break;
        int uid = X_idx[grow];
        if (uid != curUid) {
            if (curUid >= 0) {
                #pragma unroll
                for (int j = 0; j < 4; j++) {
                    int c = tx * 4 + j;
                    atomicAdd(&g_sum_inv[curUid * D_OUT + c], aInv[j]);
                    atomicAdd(&g_sum_minv[curUid * D_OUT + c], aMinv[j]);
                }
            }
            curUid = uid;
            #pragma unroll
            for (int j = 0; j < 4; j++) { aInv[j] = 0.f; aMinv[j] = 0.f; }
        }
        #pragma unroll
        for (int j = 0; j < 4; j++) {
            float v   = fmaxf(accV[i][j], EPS);
            float inv = 1.f / v;
            aInv[j]  += inv;
            aMinv[j] += accM[i][j] * inv;
        }
    }
    if (curUid >= 0) {
        #pragma unroll
        for (int j = 0; j < 4; j++) {
            int c = tx * 4 + j;
            atomicAdd(&g_sum_inv[curUid * D_OUT + c], aInv[j]);
            atomicAdd(&g_sum_minv[curUid * D_OUT + c], aMinv[j]);
        }
    }
}

// ---------------- finalize --------------------------------------------------
__global__ __launch_bounds__(256) void finalize_kernel(float* __restrict__ out) {
    int id = blockIdx.x * 256 + threadIdx.x;
    if (id < U_DIM * D_OUT) {
        float var = 1.f / (g_sum_inv[id] + EPS);
        out[id]                 = g_sum_minv[id] * var;  // emb_mean
        out[U_DIM * D_OUT + id] = var;                   // emb_var
    }
}

// ---------------- launch ----------------------------------------------------
extern "C" void kernel_launch(void* const* d_in, const int* in_sizes, int n_in,
                              void* d_out, int out_size) {
    const float* X     = (const float*)d_in[0];
    const int*   X_idx = (const int*)d_in[1];
    const float* Wmu0  = (const float*)d_in[2];
    const float* Wlv0  = (const float*)d_in[3];
    const float* Wmu1  = (const float*)d_in[4];
    const float* Wlv1  = (const float*)d_in[5];
    float* out = (float*)d_out;

    (void)in_sizes; (void)n_in; (void)out_size;

    const int nRowTiles = (N_ROWS + 63) / 64;

    prep_kernel<<<(U_DIM * D_OUT + 255) / 256, 256>>>(Wlv0, Wmu1, Wlv1);

    dim3 g0(nRowTiles, R_DIM / 64);
    layer0_kernel<<<g0, 256>>>(X, Wmu0);

    layer1_agg_kernel<<<nRowTiles, 256>>>(X_idx, Wmu1);

    finalize_kernel<<<(U_DIM * D_OUT + 255) / 256, 256>>>(out);
}

// round 3
// speedup vs baseline: 1.5601x; 1.5601x over previous
#include <cuda_runtime.h>
#include <cuda_bf16.h>
#include <cstdint>
#include <cstddef>

#define N_ROWS 500000
#define D_IN   128
#define R_DIM  256
#define D_OUT  64
#define U_DIM  10000
#define EPS    1e-8f

// ---------------- device scratch --------------------------------------------
__device__ float g_m0[(size_t)N_ROWS * R_DIM];   // 512 MB
__device__ float g_v0[(size_t)N_ROWS * R_DIM];   // 512 MB
__device__ float g_sum_inv[U_DIM * D_OUT];
__device__ float g_sum_minv[U_DIM * D_OUT];

// ---------------- helpers ----------------------------------------------------
static __device__ __forceinline__ uint32_t smem_u32(const void* p) {
    uint32_t a;
    asm("{ .reg .u64 t; cvta.to.shared.u64 t, %1; cvt.u32.u64 %0, t; }"
        : "=r"(a) : "l"(p));
    return a;
}

#define LDSM4(R, addr) \
    asm volatile("ldmatrix.sync.aligned.m8n8.x4.shared.b16 {%0,%1,%2,%3}, [%4];" \
        : "=r"((R)[0]), "=r"((R)[1]), "=r"((R)[2]), "=r"((R)[3]) : "r"(addr))

static __device__ __forceinline__ void mma16816(float* c, const uint32_t* a,
                                                const uint32_t* b) {
    asm volatile("mma.sync.aligned.m16n8k16.row.col.f32.bf16.bf16.f32 "
                 "{%0,%1,%2,%3},{%4,%5,%6,%7},{%8,%9},{%0,%1,%2,%3};"
                 : "+f"(c[0]), "+f"(c[1]), "+f"(c[2]), "+f"(c[3])
                 : "r"(a[0]), "r"(a[1]), "r"(a[2]), "r"(a[3]),
                   "r"(b[0]), "r"(b[1]));
}

static __device__ __forceinline__ void split2(float x, __nv_bfloat16& h,
                                              __nv_bfloat16& l) {
    h = __float2bfloat16(x);
    l = __float2bfloat16(x - __bfloat162float(h));
}

// ---------------- prep --------------------------------------------------------
__global__ __launch_bounds__(256) void prep_kernel() {
    int id = blockIdx.x * 256 + threadIdx.x;
    if (id < U_DIM * D_OUT) { g_sum_inv[id] = 0.f; g_sum_minv[id] = 0.f; }
}

// ============================================================================
// Layer 0:  m0 = gate(X @ Wmu0),  v0 = gate * (X^2 @ exp(Wlv0))
// block = 128 rows; loops over 4 col-chunks of 64; hi/lo bf16 split (3 MMAs).
// smem layout (bytes), padded rows: 136 bf16 = 272 B (conflict-free ldmatrix)
// ============================================================================
#define L0_PAD 136
#define L0_XH  0
#define L0_XL  34816
#define L0_2H  69632
#define L0_2L  104448
#define L0_WMH 139264
#define L0_WML 156672
#define L0_WVH 174080
#define L0_WVL 191488
#define L0_SMEM 208896

__global__ __launch_bounds__(256, 1) void layer0_mma(const float* __restrict__ X,
                                                     const float* __restrict__ Wmu0,
                                                     const float* __restrict__ Wlv0) {
    extern __shared__ char sm[];
    const uint32_t sb = smem_u32(sm);
    const int t = threadIdx.x, lane = t & 31, wid = t >> 5;
    const int wm = wid >> 1, wn = wid & 1;         // 4 x 2 warp grid
    const int rowBase = blockIdx.x * 128;

    // ---- X tile: 128 rows x 128 K; build hi/lo of x and x^2 ----------------
    #pragma unroll
    for (int it = 0; it < 16; it++) {
        int idx = t + it * 256;
        int row = idx >> 5;
        int k4  = (idx & 31) * 4;
        float4 v = make_float4(0.f, 0.f, 0.f, 0.f);
        if (rowBase + row < N_ROWS)
            v = *(const float4*)&X[(size_t)(rowBase + row) * D_IN + k4];
        const float xs[4] = {v.x, v.y, v.z, v.w};
        #pragma unroll
        for (int e = 0; e < 4; e++) {
            __nv_bfloat16 h, l, h2, l2;
            split2(xs[e], h, l);
            split2(xs[e] * xs[e], h2, l2);
            int o = (row * L0_PAD + k4 + e) * 2;
            *(__nv_bfloat16*)(sm + L0_XH + o) = h;
            *(__nv_bfloat16*)(sm + L0_XL + o) = l;
            *(__nv_bfloat16*)(sm + L0_2H + o) = h2;
            *(__nv_bfloat16*)(sm + L0_2L + o) = l2;
        }
    }

    const int lr = lane & 7, sel = lane >> 3;

    for (int nc = 0; nc < 4; nc++) {
        // ---- weights for this 64-col chunk: [n][k], exp on the fly ----------
        #pragma unroll
        for (int it = 0; it < 32; it++) {
            int idx = t + it * 256;
            int k = idx >> 6, n = idx & 63;
            size_t go = (size_t)k * R_DIM + nc * 64 + n;
            float wmv = Wmu0[go];
            float wvv = expf(Wlv0[go]);
            int o = (n * L0_PAD + k) * 2;
            __nv_bfloat16 h, l;
            split2(wmv, h, l);
            *(__nv_bfloat16*)(sm + L0_WMH + o) = h;
            *(__nv_bfloat16*)(sm + L0_WML + o) = l;
            split2(wvv, h, l);
            *(__nv_bfloat16*)(sm + L0_WVH + o) = h;
            *(__nv_bfloat16*)(sm + L0_WVL + o) = l;
        }
        __syncthreads();

        float accM[2][4][4], accV[2][4][4];
        #pragma unroll
        for (int a = 0; a < 2; a++)
            #pragma unroll
            for (int b = 0; b < 4; b++)
                #pragma unroll
                for (int c = 0; c < 4; c++) { accM[a][b][c] = 0.f; accV[a][b][c] = 0.f; }

        #pragma unroll
        for (int ks = 0; ks < 8; ks++) {
            const int k = ks * 16;
            uint32_t Axh[2][4], Axl[2][4], A2h[2][4], A2l[2][4];
            #pragma unroll
            for (int rf = 0; rf < 2; rf++) {
                int ar = wm * 32 + rf * 16 + lr + (sel & 1) * 8;
                int ac = k + (sel >> 1) * 8;
                uint32_t off = (uint32_t)(ar * L0_PAD + ac) * 2;
                LDSM4(Axh[rf], sb + L0_XH + off);
                LDSM4(Axl[rf], sb + L0_XL + off);
                LDSM4(A2h[rf], sb + L0_2H + off);
                LDSM4(A2l[rf], sb + L0_2L + off);
            }
            #pragma unroll
            for (int hh = 0; hh < 2; hh++) {
                uint32_t Bmh[4], Bml[4], Bvh[4], Bvl[4];
                int br = wn * 32 + hh * 16 + lr + (sel >> 1) * 8;
                int bc = k + (sel & 1) * 8;
                uint32_t off = (uint32_t)(br * L0_PAD + bc) * 2;
                LDSM4(Bmh, sb + L0_WMH + off);
                LDSM4(Bml, sb + L0_WML + off);
                LDSM4(Bvh, sb + L0_WVH + off);
                LDSM4(Bvl, sb + L0_WVL + off);
                #pragma unroll
                for (int rf = 0; rf < 2; rf++) {
                    #pragma unroll
                    for (int cq = 0; cq < 2; cq++) {
                        int cf = hh * 2 + cq, o2 = cq * 2;
                        mma16816(accM[rf][cf], Axh[rf], &Bmh[o2]);
                        mma16816(accM[rf][cf], Axh[rf], &Bml[o2]);
                        mma16816(accM[rf][cf], Axl[rf], &Bmh[o2]);
                        mma16816(accV[rf][cf], A2h[rf], &Bvh[o2]);
                        mma16816(accV[rf][cf], A2h[rf], &Bvl[o2]);
                        mma16816(accV[rf][cf], A2l[rf], &Bvh[o2]);
                    }
                }
            }
        }

        // ---- epilogue: relu gate + fp32 scratch spill ------------------------
        #pragma unroll
        for (int rf = 0; rf < 2; rf++) {
            #pragma unroll
            for (int cf = 0; cf < 4; cf++) {
                int c = nc * 64 + wn * 32 + cf * 8 + 2 * (lane & 3);
                #pragma unroll
                for (int half = 0; half < 2; half++) {
                    int r = rowBase + wm * 32 + rf * 16 + (lane >> 2) + half * 8;
                    if (r < N_ROWS) {
                        float m0 = accM[rf][cf][half * 2 + 0];
                        float m1 = accM[rf][cf][half * 2 + 1];
                        float v0 = accV[rf][cf][half * 2 + 0];
                        float v1 = accV[rf][cf][half * 2 + 1];
                        bool g0 = m0 > 0.f, g1 = m1 > 0.f;
                        float2 mo = make_float2(g0 ? m0 : 0.f, g1 ? m1 : 0.f);
                        float2 vo = make_float2(g0 ? v0 : 0.f, g1 ? v1 : 0.f);
                        *(float2*)&g_m0[(size_t)r * R_DIM + c] = mo;
                        *(float2*)&g_v0[(size_t)r * R_DIM + c] = vo;
                    }
                }
            }
        }
        __syncthreads();
    }
}

// ============================================================================
// Layer 1 + aggregation:  M = m@Wmu1 ; V = v@(Wmu1^2+Wvar1) + m^2@Wvar1
// block = 128 rows, N = 64 (full D_OUT), K streamed in 4 chunks of 64.
// ============================================================================
#define L1_PAD 72
#define L1_MH  0
#define L1_ML  18432
#define L1_VH  36864
#define L1_VL  55296
#define L1_2H  73728
#define L1_2L  92160
#define L1_BMH 110592
#define L1_BML 119808
#define L1_A1H 129024
#define L1_A1L 138240
#define L1_BVH 147456
#define L1_BVL 156672
#define L1_UID 165888
#define L1_SINV  0          // staging overlaps A region (post-GEMM only)
#define L1_SMINV 33280
#define L1_SMEM 166400

__global__ __launch_bounds__(256, 1) void layer1_mma(const int* __restrict__ X_idx,
                                                     const float* __restrict__ Wmu1,
                                                     const float* __restrict__ Wlv1) {
    extern __shared__ char sm[];
    const uint32_t sb = smem_u32(sm);
    const int t = threadIdx.x, lane = t & 31, wid = t >> 5;
    const int wm = wid >> 1, wn = wid & 1;
    const int rowBase = blockIdx.x * 128;

    if (t < 128) {
        int r = rowBase + t;
        *(int*)(sm + L1_UID + t * 4) = (r < N_ROWS) ? X_idx[r] : -1;
    }

    const int lr = lane & 7, sel = lane >> 3;

    float accM[2][4][4], accV[2][4][4];
    #pragma unroll
    for (int a = 0; a < 2; a++)
        #pragma unroll
        for (int b = 0; b < 4; b++)
            #pragma unroll
            for (int c = 0; c < 4; c++) { accM[a][b][c] = 0.f; accV[a][b][c] = 0.f; }

    for (int kc = 0; kc < 4; kc++) {
        // ---- A chunk: m/v fp32 scratch -> hi/lo; build m^2 hi/lo -------------
        #pragma unroll
        for (int it = 0; it < 8; it++) {
            int idx = t + it * 256;           // 0..2047
            int row = idx >> 4;
            int k4  = (idx & 15) * 4;
            float4 mv = make_float4(0.f, 0.f, 0.f, 0.f);
            float4 vv = mv;
            int r = rowBase + row;
            if (r < N_ROWS) {
                size_t go = (size_t)r * R_DIM + kc * 64 + k4;
                mv = *(const float4*)&g_m0[go];
                vv = *(const float4*)&g_v0[go];
            }
            const float ms[4] = {mv.x, mv.y, mv.z, mv.w};
            const float vs[4] = {vv.x, vv.y, vv.z, vv.w};
            #pragma unroll
            for (int e = 0; e < 4; e++) {
                int o = (row * L1_PAD + k4 + e) * 2;
                __nv_bfloat16 h, l;
                split2(ms[e], h, l);
                *(__nv_bfloat16*)(sm + L1_MH + o) = h;
                *(__nv_bfloat16*)(sm + L1_ML + o) = l;
                split2(vs[e], h, l);
                *(__nv_bfloat16*)(sm + L1_VH + o) = h;
                *(__nv_bfloat16*)(sm + L1_VL + o) = l;
                split2(ms[e] * ms[e], h, l);
                *(__nv_bfloat16*)(sm + L1_2H + o) = h;
                *(__nv_bfloat16*)(sm + L1_2L + o) = l;
            }
        }
        // ---- B chunk: Wmu1 / (Wmu1^2+Wvar1) / Wvar1, hi/lo, [n][k] ----------
        #pragma unroll
        for (int it = 0; it < 4; it++) {
            int idx = t + it * 256;           // 0..1023
            int k  = idx >> 4;
            int n4 = (idx & 15) * 4;
            size_t go = (size_t)(kc * 64 + k) * D_OUT + n4;
            float4 wmu = *(const float4*)&Wmu1[go];
            float4 wlv = *(const float4*)&Wlv1[go];
            const float wm_[4] = {wmu.x, wmu.y, wmu.z, wmu.w};
            const float wl_[4] = {wlv.x, wlv.y, wlv.z, wlv.w};
            #pragma unroll
            for (int e = 0; e < 4; e++) {
                float ev = expf(wl_[e]);
                float a1 = wm_[e] * wm_[e] + ev;
                int o = ((n4 + e) * L1_PAD + k) * 2;
                __nv_bfloat16 h, l;
                split2(wm_[e], h, l);
                *(__nv_bfloat16*)(sm + L1_BMH + o) = h;
                *(__nv_bfloat16*)(sm + L1_BML + o) = l;
                split2(a1, h, l);
                *(__nv_bfloat16*)(sm + L1_A1H + o) = h;
                *(__nv_bfloat16*)(sm + L1_A1L + o) = l;
                split2(ev, h, l);
                *(__nv_bfloat16*)(sm + L1_BVH + o) = h;
                *(__nv_bfloat16*)(sm + L1_BVL + o) = l;
            }
        }
        __syncthreads();

        #pragma unroll
        for (int ks = 0; ks < 4; ks++) {
            const int k = ks * 16;
            uint32_t Amh[2][4], Aml[2][4], Avh[2][4], Avl[2][4], A2h[2][4], A2l[2][4];
            #pragma unroll
            for (int rf = 0; rf < 2; rf++) {
                int ar = wm * 32 + rf * 16 + lr + (sel & 1) * 8;
                int ac = k + (sel >> 1) * 8;
                uint32_t off = (uint32_t)(ar * L1_PAD + ac) * 2;
                LDSM4(Amh[rf], sb + L1_MH + off);
                LDSM4(Aml[rf], sb + L1_ML + off);
                LDSM4(Avh[rf], sb + L1_VH + off);
                LDSM4(Avl[rf], sb + L1_VL + off);
                LDSM4(A2h[rf], sb + L1_2H + off);
                LDSM4(A2l[rf], sb + L1_2L + off);
            }
            #pragma unroll
            for (int hh = 0; hh < 2; hh++) {
                uint32_t Bmh[4], Bml[4], B1h[4], B1l[4], Bvh[4], Bvl[4];
                int br = wn * 32 + hh * 16 + lr + (sel >> 1) * 8;
                int bc = k + (sel & 1) * 8;
                uint32_t off = (uint32_t)(br * L1_PAD + bc) * 2;
                LDSM4(Bmh, sb + L1_BMH + off);
                LDSM4(Bml, sb + L1_BML + off);
                LDSM4(B1h, sb + L1_A1H + off);
                LDSM4(B1l, sb + L1_A1L + off);
                LDSM4(Bvh, sb + L1_BVH + off);
                LDSM4(Bvl, sb + L1_BVL + off);
                #pragma unroll
                for (int rf = 0; rf < 2; rf++) {
                    #pragma unroll
                    for (int cq = 0; cq < 2; cq++) {
                        int cf = hh * 2 + cq, o2 = cq * 2;
                        mma16816(accM[rf][cf], Amh[rf], &Bmh[o2]);
                        mma16816(accM[rf][cf], Amh[rf], &Bml[o2]);
                        mma16816(accM[rf][cf], Aml[rf], &Bmh[o2]);
                        mma16816(accV[rf][cf], Avh[rf], &B1h[o2]);
                        mma16816(accV[rf][cf], Avh[rf], &B1l[o2]);
                        mma16816(accV[rf][cf], Avl[rf], &B1h[o2]);
                        mma16816(accV[rf][cf], A2h[rf], &Bvh[o2]);
                        mma16816(accV[rf][cf], A2h[rf], &Bvl[o2]);
                        mma16816(accV[rf][cf], A2l[rf], &Bvh[o2]);
                    }
                }
            }
        }
        __syncthreads();
    }

    // ---- epilogue: inv-variance weighting into smem staging ------------------
    float* sInv  = (float*)(sm + L1_SINV);
    float* sMinv = (float*)(sm + L1_SMINV);
    #pragma unroll
    for (int rf = 0; rf < 2; rf++) {
        #pragma unroll
        for (int cf = 0; cf < 4; cf++) {
            int col = wn * 32 + cf * 8 + 2 * (lane & 3);
            #pragma unroll
            for (int half = 0; half < 2; half++) {
                int lrow = wm * 32 + rf * 16 + (lane >> 2) + half * 8;
                float m0 = accM[rf][cf][half * 2 + 0];
                float m1 = accM[rf][cf][half * 2 + 1];
                float V0 = fmaxf(accV[rf][cf][half * 2 + 0], EPS);
                float V1 = fmaxf(accV[rf][cf][half * 2 + 1], EPS);
                float i0 = 1.f / V0, i1 = 1.f / V1;
                sInv[lrow * 65 + col]      = i0;
                sInv[lrow * 65 + col + 1]  = i1;
                sMinv[lrow * 65 + col]     = m0 * i0;
                sMinv[lrow * 65 + col + 1] = m1 * i1;
            }
        }
    }
    __syncthreads();

    // ---- block-level segmented reduce over sorted uids -> atomics -----------
    const int* uids = (const int*)(sm + L1_UID);
    int col = t & 63, grp = t >> 6;
    float aI = 0.f, aM = 0.f;
    int cur = -1;
    for (int r0 = 0; r0 < 32; r0++) {
        int row = grp * 32 + r0;
        int uid = uids[row];
        if (uid != cur) {
            if (cur >= 0) {
                atomicAdd(&g_sum_inv[cur * D_OUT + col], aI);
                atomicAdd(&g_sum_minv[cur * D_OUT + col], aM);
            }
            cur = uid; aI = 0.f; aM = 0.f;
        }
        if (uid >= 0) {
            aI += sInv[row * 65 + col];
            aM += sMinv[row * 65 + col];
        }
    }
    if (cur >= 0) {
        atomicAdd(&g_sum_inv[cur * D_OUT + col], aI);
        atomicAdd(&g_sum_minv[cur * D_OUT + col], aM);
    }
}

// ---------------- finalize ----------------------------------------------------
__global__ __launch_bounds__(256) void finalize_kernel(float* __restrict__ out) {
    int id = blockIdx.x * 256 + threadIdx.x;
    if (id < U_DIM * D_OUT) {
        float var = 1.f / (g_sum_inv[id] + EPS);
        out[id]                 = g_sum_minv[id] * var;
        out[U_DIM * D_OUT + id] = var;
    }
}

// ---------------- launch -------------------------------------------------------
extern "C" void kernel_launch(void* const* d_in, const int* in_sizes, int n_in,
                              void* d_out, int out_size) {
    const float* X     = (const float*)d_in[0];
    const int*   X_idx = (const int*)d_in[1];
    const float* Wmu0  = (const float*)d_in[2];
    const float* Wlv0  = (const float*)d_in[3];
    const float* Wmu1  = (const float*)d_in[4];
    const float* Wlv1  = (const float*)d_in[5];
    float* out = (float*)d_out;
    (void)in_sizes; (void)n_in; (void)out_size;

    cudaFuncSetAttribute(layer0_mma, cudaFuncAttributeMaxDynamicSharedMemorySize, L0_SMEM);
    cudaFuncSetAttribute(layer1_mma, cudaFuncAttributeMaxDynamicSharedMemorySize, L1_SMEM);

    const int nBlocks = (N_ROWS + 127) / 128;

    prep_kernel<<<(U_DIM * D_OUT + 255) / 256, 256>>>();
    layer0_mma<<<nBlocks, 256, L0_SMEM>>>(X, Wmu0, Wlv0);
    layer1_mma<<<nBlocks, 256, L1_SMEM>>>(X_idx, Wmu1, Wlv1);
    finalize_kernel<<<(U_DIM * D_OUT + 255) / 256, 256>>>(out);
}

// round 4
// speedup vs baseline: 2.9965x; 1.9206x over previous
#include <cuda_runtime.h>
#include <cuda_bf16.h>
#include <cstdint>
#include <cstddef>

#define N_ROWS 500000
#define D_IN   128
#define R_DIM  256
#define D_OUT  64
#define U_DIM  10000
#define EPS    1e-8f
#define BM     64          // rows per block

// ---------------- precomputed weights (bf16, [n][k] layout) -----------------
__device__ __nv_bfloat16 g_w0mh[R_DIM * D_IN];
__device__ __nv_bfloat16 g_w0ml[R_DIM * D_IN];
__device__ __nv_bfloat16 g_w0vh[R_DIM * D_IN];
__device__ __nv_bfloat16 g_w1mh[D_OUT * R_DIM];
__device__ __nv_bfloat16 g_w1ml[D_OUT * R_DIM];
__device__ __nv_bfloat16 g_w1a1[D_OUT * R_DIM];
__device__ __nv_bfloat16 g_w1vh[D_OUT * R_DIM];
__device__ float g_sum_inv[U_DIM * D_OUT];
__device__ float g_sum_minv[U_DIM * D_OUT];

// ---------------- smem layout (bytes from dynamic base) ---------------------
// pitch P0 = 136 bf16 (272 B) for 128-wide K; P1 = 72 bf16 (144 B) for 64-wide
#define P0 136
#define P1 72
#define S_XH    0           // 64*272 = 17408
#define S_XL    17408
#define S_X2H   34816
#define S_W0MH  52224
#define S_W0ML  69632
#define S_W0VH  87040
#define S_L1MH  104448      // 64*144 = 9216
#define S_L1ML  113664
#define S_L1VH  122880
#define S_L12H  132096
#define S_W1MH  141312
#define S_W1ML  150528
#define S_W1A1  159744
#define S_W1VH  168960
#define S_UID   178176      // 64*4
#define S_SINV  0           // staging overlays X region (post-GEMM)
#define S_SMINV 17408
#define SMEM_SZ 178432

// ---------------- helpers ----------------------------------------------------
static __device__ __forceinline__ uint32_t smem_u32(const void* p) {
    uint32_t a;
    asm("{ .reg .u64 t; cvta.to.shared.u64 t, %1; cvt.u32.u64 %0, t; }"
        : "=r"(a) : "l"(p));
    return a;
}
#define LDSM4(R, addr) \
    asm volatile("ldmatrix.sync.aligned.m8n8.x4.shared.b16 {%0,%1,%2,%3}, [%4];" \
        : "=r"((R)[0]), "=r"((R)[1]), "=r"((R)[2]), "=r"((R)[3]) : "r"(addr))

static __device__ __forceinline__ void mma16816(float* c, const uint32_t* a,
                                                const uint32_t* b) {
    asm volatile("mma.sync.aligned.m16n8k16.row.col.f32.bf16.bf16.f32 "
                 "{%0,%1,%2,%3},{%4,%5,%6,%7},{%8,%9},{%0,%1,%2,%3};"
                 : "+f"(c[0]), "+f"(c[1]), "+f"(c[2]), "+f"(c[3])
                 : "r"(a[0]), "r"(a[1]), "r"(a[2]), "r"(a[3]),
                   "r"(b[0]), "r"(b[1]));
}
static __device__ __forceinline__ void split2(float x, __nv_bfloat16& h,
                                              __nv_bfloat16& l) {
    h = __float2bfloat16(x);
    l = __float2bfloat16(x - __bfloat162float(h));
}
static __device__ __forceinline__ uint32_t pk(__nv_bfloat16 a, __nv_bfloat16 b) {
    return (uint32_t)__bfloat16_as_ushort(a) | ((uint32_t)__bfloat16_as_ushort(b) << 16);
}

// ---------------- prep: weight conversion + accumulator zero ----------------
__global__ __launch_bounds__(256) void prep_kernel(const float* __restrict__ Wmu0,
                                                   const float* __restrict__ Wlv0,
                                                   const float* __restrict__ Wmu1,
                                                   const float* __restrict__ Wlv1) {
    int id = blockIdx.x * 256 + threadIdx.x;
    if (id < R_DIM * D_IN) {                  // n = id/128, k = id%128
        int n = id >> 7, k = id & 127;
        float wm = Wmu0[(size_t)k * R_DIM + n];
        float wv = expf(Wlv0[(size_t)k * R_DIM + n]);
        __nv_bfloat16 h, l;
        split2(wm, h, l);
        g_w0mh[id] = h;
        g_w0ml[id] = l;
        g_w0vh[id] = __float2bfloat16(wv);
    }
    if (id < D_OUT * R_DIM) {                 // n = id/256, k = id%256
        int n = id >> 8, k = id & 255;
        float wm = Wmu1[(size_t)k * D_OUT + n];
        float e  = expf(Wlv1[(size_t)k * D_OUT + n]);
        __nv_bfloat16 h, l;
        split2(wm, h, l);
        g_w1mh[id] = h;
        g_w1ml[id] = l;
        g_w1a1[id] = __float2bfloat16(wm * wm + e);
        g_w1vh[id] = __float2bfloat16(e);
    }
    if (id < U_DIM * D_OUT) { g_sum_inv[id] = 0.f; g_sum_minv[id] = 0.f; }
}

// ============================================================================
// Fused kernel: layer0 + layer1 + aggregation. 64 rows / block, 256 threads.
// Warp grid 2(m) x 4(n): warp tile 32 x 16 for both layers.
// ============================================================================
__global__ __launch_bounds__(256, 1) void fused_kernel(const float* __restrict__ X,
                                                       const int* __restrict__ X_idx) {
    extern __shared__ char sm[];
    const uint32_t sb = smem_u32(sm);
    const int t = threadIdx.x, lane = t & 31, wid = t >> 5;
    const int wm_ = wid >> 2, wn = wid & 3;
    const int rowBase = blockIdx.x * BM;
    const int lr = lane & 7, sel = lane >> 3;

    if (t < BM) {
        int r = rowBase + t;
        *(int*)(sm + S_UID + t * 4) = (r < N_ROWS) ? X_idx[r] : -1;
    }

    // ---- phase 0: X tile 64 x 128; split to xh / xl / x2h -------------------
    #pragma unroll
    for (int it = 0; it < 8; it++) {
        int idx = t + it * 256;
        int row = idx >> 5;
        int k4  = (idx & 31) * 4;
        float4 v = make_float4(0.f, 0.f, 0.f, 0.f);
        if (rowBase + row < N_ROWS)
            v = *(const float4*)&X[(size_t)(rowBase + row) * D_IN + k4];
        const float xs[4] = {v.x, v.y, v.z, v.w};
        __nv_bfloat16 h[4], l[4], q[4];
        #pragma unroll
        for (int e = 0; e < 4; e++) {
            split2(xs[e], h[e], l[e]);
            q[e] = __float2bfloat16(xs[e] * xs[e]);
        }
        int o = (row * P0 + k4) * 2;
        *(uint32_t*)(sm + S_XH  + o)     = pk(h[0], h[1]);
        *(uint32_t*)(sm + S_XH  + o + 4) = pk(h[2], h[3]);
        *(uint32_t*)(sm + S_XL  + o)     = pk(l[0], l[1]);
        *(uint32_t*)(sm + S_XL  + o + 4) = pk(l[2], l[3]);
        *(uint32_t*)(sm + S_X2H + o)     = pk(q[0], q[1]);
        *(uint32_t*)(sm + S_X2H + o + 4) = pk(q[2], q[3]);
    }

    float accM1[2][2][4], accV1[2][2][4];
    #pragma unroll
    for (int a = 0; a < 2; a++)
        #pragma unroll
        for (int b = 0; b < 2; b++)
            #pragma unroll
            for (int c = 0; c < 4; c++) { accM1[a][b][c] = 0.f; accV1[a][b][c] = 0.f; }

    for (int nc = 0; nc < 4; nc++) {
        // ---- phase 1: W0 chunk [64n x 128k] bf16 loads (uint4 = 8 bf16) -----
        #pragma unroll
        for (int it = 0; it < 4; it++) {
            int idx = t + it * 256;
            int n = idx >> 4;
            int k8 = (idx & 15) * 8;
            size_t go = (size_t)(nc * 64 + n) * D_IN + k8;
            int o = (n * P0 + k8) * 2;
            *(uint4*)(sm + S_W0MH + o) = *(const uint4*)&g_w0mh[go];
            *(uint4*)(sm + S_W0ML + o) = *(const uint4*)&g_w0ml[go];
            *(uint4*)(sm + S_W0VH + o) = *(const uint4*)&g_w0vh[go];
        }
        __syncthreads();

        // ---- phase 2: layer0 MMA (M 3-term, V 1-term) ------------------------
        float aM[2][2][4], aV[2][2][4];
        #pragma unroll
        for (int a = 0; a < 2; a++)
            #pragma unroll
            for (int b = 0; b < 2; b++)
                #pragma unroll
                for (int c = 0; c < 4; c++) { aM[a][b][c] = 0.f; aV[a][b][c] = 0.f; }

        #pragma unroll
        for (int ks = 0; ks < 8; ks++) {
            const int k = ks * 16;
            uint32_t Axh[2][4], Axl[2][4], A2h[2][4];
            #pragma unroll
            for (int rf = 0; rf < 2; rf++) {
                int ar = wm_ * 32 + rf * 16 + lr + (sel & 1) * 8;
                int ac = k + (sel >> 1) * 8;
                uint32_t off = (uint32_t)(ar * P0 + ac) * 2;
                LDSM4(Axh[rf], sb + S_XH + off);
                LDSM4(Axl[rf], sb + S_XL + off);
                LDSM4(A2h[rf], sb + S_X2H + off);
            }
            uint32_t Bmh[4], Bml[4], Bvh[4];
            {
                int br = wn * 16 + lr + (sel >> 1) * 8;
                int bc = k + (sel & 1) * 8;
                uint32_t off = (uint32_t)(br * P0 + bc) * 2;
                LDSM4(Bmh, sb + S_W0MH + off);
                LDSM4(Bml, sb + S_W0ML + off);
                LDSM4(Bvh, sb + S_W0VH + off);
            }
            #pragma unroll
            for (int rf = 0; rf < 2; rf++) {
                #pragma unroll
                for (int cq = 0; cq < 2; cq++) {
                    int o2 = cq * 2;
                    mma16816(aM[rf][cq], Axh[rf], &Bmh[o2]);
                    mma16816(aM[rf][cq], Axh[rf], &Bml[o2]);
                    mma16816(aM[rf][cq], Axl[rf], &Bmh[o2]);
                    mma16816(aV[rf][cq], A2h[rf], &Bvh[o2]);
                }
            }
        }

        // ---- phase 3: gate + split into layer1 A region ----------------------
        #pragma unroll
        for (int rf = 0; rf < 2; rf++) {
            #pragma unroll
            for (int cf = 0; cf < 2; cf++) {
                int klocal = wn * 16 + cf * 8 + 2 * (lane & 3);
                #pragma unroll
                for (int half = 0; half < 2; half++) {
                    int lrow = wm_ * 32 + rf * 16 + (lane >> 2) + half * 8;
                    float m0 = aM[rf][cf][half * 2 + 0];
                    float m1 = aM[rf][cf][half * 2 + 1];
                    float v0 = aV[rf][cf][half * 2 + 0];
                    float v1 = aV[rf][cf][half * 2 + 1];
                    bool g0 = m0 > 0.f, g1 = m1 > 0.f;
                    m0 = g0 ? m0 : 0.f;  v0 = g0 ? v0 : 0.f;
                    m1 = g1 ? m1 : 0.f;  v1 = g1 ? v1 : 0.f;
                    __nv_bfloat16 h0, l0, h1, l1;
                    split2(m0, h0, l0);
                    split2(m1, h1, l1);
                    int o = (lrow * P1 + klocal) * 2;
                    *(uint32_t*)(sm + S_L1MH + o) = pk(h0, h1);
                    *(uint32_t*)(sm + S_L1ML + o) = pk(l0, l1);
                    *(uint32_t*)(sm + S_L1VH + o) =
                        pk(__float2bfloat16(v0), __float2bfloat16(v1));
                    *(uint32_t*)(sm + S_L12H + o) =
                        pk(__float2bfloat16(m0 * m0), __float2bfloat16(m1 * m1));
                }
            }
        }

        // ---- phase 4: W1 chunk [64n x 64k] bf16 loads -------------------------
        #pragma unroll
        for (int it = 0; it < 2; it++) {
            int idx = t + it * 256;
            int n = idx >> 3;
            int k8 = (idx & 7) * 8;
            size_t go = (size_t)n * R_DIM + nc * 64 + k8;
            int o = (n * P1 + k8) * 2;
            *(uint4*)(sm + S_W1MH + o) = *(const uint4*)&g_w1mh[go];
            *(uint4*)(sm + S_W1ML + o) = *(const uint4*)&g_w1ml[go];
            *(uint4*)(sm + S_W1A1 + o) = *(const uint4*)&g_w1a1[go];
            *(uint4*)(sm + S_W1VH + o) = *(const uint4*)&g_w1vh[go];
        }
        __syncthreads();

        // ---- phase 5: layer1 MMA accumulate (M 3-term, V 2-term) --------------
        #pragma unroll
        for (int ks = 0; ks < 4; ks++) {
            const int k = ks * 16;
            uint32_t Amh[2][4], Aml[2][4], Avh[2][4], A2m[2][4];
            #pragma unroll
            for (int rf = 0; rf < 2; rf++) {
                int ar = wm_ * 32 + rf * 16 + lr + (sel & 1) * 8;
                int ac = k + (sel >> 1) * 8;
                uint32_t off = (uint32_t)(ar * P1 + ac) * 2;
                LDSM4(Amh[rf], sb + S_L1MH + off);
                LDSM4(Aml[rf], sb + S_L1ML + off);
                LDSM4(Avh[rf], sb + S_L1VH + off);
                LDSM4(A2m[rf], sb + S_L12H + off);
            }
            uint32_t Bm[4], Bl[4], Ba[4], Bv[4];
            {
                int br = wn * 16 + lr + (sel >> 1) * 8;
                int bc = k + (sel & 1) * 8;
                uint32_t off = (uint32_t)(br * P1 + bc) * 2;
                LDSM4(Bm, sb + S_W1MH + off);
                LDSM4(Bl, sb + S_W1ML + off);
                LDSM4(Ba, sb + S_W1A1 + off);
                LDSM4(Bv, sb + S_W1VH + off);
            }
            #pragma unroll
            for (int rf = 0; rf < 2; rf++) {
                #pragma unroll
                for (int cq = 0; cq < 2; cq++) {
                    int o2 = cq * 2;
                    mma16816(accM1[rf][cq], Amh[rf], &Bm[o2]);
                    mma16816(accM1[rf][cq], Amh[rf], &Bl[o2]);
                    mma16816(accM1[rf][cq], Aml[rf], &Bm[o2]);
                    mma16816(accV1[rf][cq], Avh[rf], &Ba[o2]);
                    mma16816(accV1[rf][cq], A2m[rf], &Bv[o2]);
                }
            }
        }
        // next iteration's first __syncthreads() provides the cross-phase fence
    }

    // ---- epilogue: inv-variance weighting into smem staging -------------------
    __syncthreads();           // all phase-5 reads done before overlaying X region
    float* sInv  = (float*)(sm + S_SINV);
    float* sMinv = (float*)(sm + S_SMINV);
    #pragma unroll
    for (int rf = 0; rf < 2; rf++) {
        #pragma unroll
        for (int cf = 0; cf < 2; cf++) {
            int col = wn * 16 + cf * 8 + 2 * (lane & 3);
            #pragma unroll
            for (int half = 0; half < 2; half++) {
                int lrow = wm_ * 32 + rf * 16 + (lane >> 2) + half * 8;
                float m0 = accM1[rf][cf][half * 2 + 0];
                float m1 = accM1[rf][cf][half * 2 + 1];
                float V0 = fmaxf(accV1[rf][cf][half * 2 + 0], EPS);
                float V1 = fmaxf(accV1[rf][cf][half * 2 + 1], EPS);
                float i0 = 1.f / V0, i1 = 1.f / V1;
                sInv[lrow * 65 + col]      = i0;
                sInv[lrow * 65 + col + 1]  = i1;
                sMinv[lrow * 65 + col]     = m0 * i0;
                sMinv[lrow * 65 + col + 1] = m1 * i1;
            }
        }
    }
    __syncthreads();

    // ---- block-level segmented reduce over sorted uids -> atomics -------------
    const int* uids = (const int*)(sm + S_UID);
    int col = t & 63, grp = t >> 6;            // 4 groups x 16 rows
    float aI = 0.f, aM = 0.f;
    int cur = -1;
    for (int r0 = 0; r0 < 16; r0++) {
        int row = grp * 16 + r0;
        int uid = uids[row];
        if (uid != cur) {
            if (cur >= 0) {
                atomicAdd(&g_sum_inv[cur * D_OUT + col], aI);
                atomicAdd(&g_sum_minv[cur * D_OUT + col], aM);
            }
            cur = uid; aI = 0.f; aM = 0.f;
        }
        if (uid >= 0) {
            aI += sInv[row * 65 + col];
            aM += sMinv[row * 65 + col];
        }
    }
    if (cur >= 0) {
        atomicAdd(&g_sum_inv[cur * D_OUT + col], aI);
        atomicAdd(&g_sum_minv[cur * D_OUT + col], aM);
    }
}

// ---------------- finalize ----------------------------------------------------
__global__ __launch_bounds__(256) void finalize_kernel(float* __restrict__ out) {
    int id = blockIdx.x * 256 + threadIdx.x;
    if (id < U_DIM * D_OUT) {
        float var = 1.f / (g_sum_inv[id] + EPS);
        out[id]                 = g_sum_minv[id] * var;
        out[U_DIM * D_OUT + id] = var;
    }
}

// ---------------- launch -------------------------------------------------------
extern "C" void kernel_launch(void* const* d_in, const int* in_sizes, int n_in,
                              void* d_out, int out_size) {
    const float* X     = (const float*)d_in[0];
    const int*   X_idx = (const int*)d_in[1];
    const float* Wmu0  = (const float*)d_in[2];
    const float* Wlv0  = (const float*)d_in[3];
    const float* Wmu1  = (const float*)d_in[4];
    const float* Wlv1  = (const float*)d_in[5];
    float* out = (float*)d_out;
    (void)in_sizes; (void)n_in; (void)out_size;

    cudaFuncSetAttribute(fused_kernel, cudaFuncAttributeMaxDynamicSharedMemorySize,
                         SMEM_SZ);

    const int nBlocks = (N_ROWS + BM - 1) / BM;

    prep_kernel<<<(U_DIM * D_OUT + 255) / 256, 256>>>(Wmu0, Wlv0, Wmu1, Wlv1);
    fused_kernel<<<nBlocks, 256, SMEM_SZ>>>(X, X_idx);
    finalize_kernel<<<(U_DIM * D_OUT + 255) / 256, 256>>>(out);
}

// round 5
// speedup vs baseline: 3.4665x; 1.1569x over previous
#include <cuda_runtime.h>
#include <cuda_bf16.h>
#include <cstdint>
#include <cstddef>

#define N_ROWS 500000
#define D_IN   128
#define R_DIM  256
#define D_OUT  64
#define U_DIM  10000
#define EPS    1e-8f
#define BM     128         // rows per block

// ---------------- precomputed weights (bf16, [n][k] layout) -----------------
__device__ __nv_bfloat16 g_w0mh[R_DIM * D_IN];
__device__ __nv_bfloat16 g_w0ml[R_DIM * D_IN];
__device__ __nv_bfloat16 g_w0vh[R_DIM * D_IN];
__device__ __nv_bfloat16 g_w1mh[D_OUT * R_DIM];
__device__ __nv_bfloat16 g_w1ml[D_OUT * R_DIM];
__device__ __nv_bfloat16 g_w1a1[D_OUT * R_DIM];
__device__ __nv_bfloat16 g_w1vh[D_OUT * R_DIM];
__device__ float g_sum_inv[U_DIM * D_OUT];
__device__ float g_sum_minv[U_DIM * D_OUT];

// ---------------- smem layout (bytes) ---------------------------------------
// P0 = 136 bf16 (272 B) pitch for 128-wide K; P1 = 40 bf16 (80 B) for 32-wide
#define P0B 272
#define P1B 80
#define S_XH     0                     // 128*272 = 34816
#define S_XL     34816
#define S_X2H    69632
#define S_W0     104448                // 2 stages x 3 mats x 32*272
#define W0_STAGE 26112
#define W0_MAT   8704
#define S_W1     156672                // 4 mats x 64*80
#define W1_MAT   5120
#define S_L1MH   177152                // 128*80 each
#define S_L1ML   187392
#define S_L1VH   197632
#define S_L12H   207872
#define S_UID    218112                // 128*4
#define SMEM_SZ  218624
#define S_SINV   0                     // staging overlays X (post-GEMM)
#define S_SMINV  34816

// ---------------- helpers ----------------------------------------------------
static __device__ __forceinline__ uint32_t smem_u32(const void* p) {
    uint32_t a;
    asm("{ .reg .u64 t; cvta.to.shared.u64 t, %1; cvt.u32.u64 %0, t; }"
        : "=r"(a) : "l"(p));
    return a;
}
#define LDSM4(R, addr) \
    asm volatile("ldmatrix.sync.aligned.m8n8.x4.shared.b16 {%0,%1,%2,%3}, [%4];" \
        : "=r"((R)[0]), "=r"((R)[1]), "=r"((R)[2]), "=r"((R)[3]) : "r"(addr))
#define CP16(s, g) \
    asm volatile("cp.async.cg.shared.global [%0], [%1], 16;" :: "r"(s), "l"(g))
#define CP_COMMIT() asm volatile("cp.async.commit_group;" ::: "memory")
#define CP_WAIT(N)  asm volatile("cp.async.wait_group %0;" :: "n"(N) : "memory")

static __device__ __forceinline__ void mma16816(float* c, const uint32_t* a,
                                                const uint32_t* b) {
    asm volatile("mma.sync.aligned.m16n8k16.row.col.f32.bf16.bf16.f32 "
                 "{%0,%1,%2,%3},{%4,%5,%6,%7},{%8,%9},{%0,%1,%2,%3};"
                 : "+f"(c[0]), "+f"(c[1]), "+f"(c[2]), "+f"(c[3])
                 : "r"(a[0]), "r"(a[1]), "r"(a[2]), "r"(a[3]),
                   "r"(b[0]), "r"(b[1]));
}
static __device__ __forceinline__ void split2(float x, __nv_bfloat16& h,
                                              __nv_bfloat16& l) {
    h = __float2bfloat16(x);
    l = __float2bfloat16(x - __bfloat162float(h));
}
static __device__ __forceinline__ uint32_t pk(__nv_bfloat16 a, __nv_bfloat16 b) {
    return (uint32_t)__bfloat16_as_ushort(a) | ((uint32_t)__bfloat16_as_ushort(b) << 16);
}

// ---------------- prep -------------------------------------------------------
__global__ __launch_bounds__(256) void prep_kernel(const float* __restrict__ Wmu0,
                                                   const float* __restrict__ Wlv0,
                                                   const float* __restrict__ Wmu1,
                                                   const float* __restrict__ Wlv1) {
    int id = blockIdx.x * 256 + threadIdx.x;
    if (id < R_DIM * D_IN) {
        int n = id >> 7, k = id & 127;
        float wm = Wmu0[(size_t)k * R_DIM + n];
        float wv = expf(Wlv0[(size_t)k * R_DIM + n]);
        __nv_bfloat16 h, l;
        split2(wm, h, l);
        g_w0mh[id] = h;
        g_w0ml[id] = l;
        g_w0vh[id] = __float2bfloat16(wv);
    }
    if (id < D_OUT * R_DIM) {
        int n = id >> 8, k = id & 255;
        float wm = Wmu1[(size_t)k * D_OUT + n];
        float e  = expf(Wlv1[(size_t)k * D_OUT + n]);
        __nv_bfloat16 h, l;
        split2(wm, h, l);
        g_w1mh[id] = h;
        g_w1ml[id] = l;
        g_w1a1[id] = __float2bfloat16(wm * wm + e);
        g_w1vh[id] = __float2bfloat16(e);
    }
    if (id < U_DIM * D_OUT) { g_sum_inv[id] = 0.f; g_sum_minv[id] = 0.f; }
}

// ============================================================================
// Fused kernel: 128 rows/block, 256 threads, warp grid 4(m) x 2(n).
// 8 weight chunks of 32; W0 double-buffered + cp.async pipelined.
// ============================================================================
__global__ __launch_bounds__(256, 1) void fused_kernel(const float* __restrict__ X,
                                                       const int* __restrict__ X_idx) {
    extern __shared__ char sm[];
    const uint32_t sb = smem_u32(sm);
    const int t = threadIdx.x, lane = t & 31, wid = t >> 5;
    const int wm_ = wid >> 1, wn = wid & 1;
    const int rowBase = blockIdx.x * BM;
    const int lr = lane & 7, sel = lane >> 3;

    // ---- prefetch W0[0] into stage 0 ----------------------------------------
    {
        const int row = t >> 4, k16 = t & 15;        // covers 32 rows x 16 units? (t<512 -> 2 its)
        #pragma unroll
        for (int it = 0; it < 2; it++) {
            int idx = t + it * 256;
            int r = idx >> 4, kk = idx & 15;
            uint32_t so = sb + S_W0 + r * P0B + kk * 16;
            CP16(so,              (const char*)&g_w0mh[(size_t)r * D_IN + kk * 8]);
            CP16(so + W0_MAT,     (const char*)&g_w0ml[(size_t)r * D_IN + kk * 8]);
            CP16(so + 2 * W0_MAT, (const char*)&g_w0vh[(size_t)r * D_IN + kk * 8]);
        }
        (void)row; (void)k16;
    }
    CP_COMMIT();

    if (t < BM) {
        int r = rowBase + t;
        *(int*)(sm + S_UID + t * 4) = (r < N_ROWS) ? X_idx[r] : -1;
    }

    // ---- phase 0: X tile 128 x 128 -> xh / xl / x2h --------------------------
    #pragma unroll
    for (int it = 0; it < 16; it++) {
        int idx = t + it * 256;
        int row = idx >> 5;
        int k4  = (idx & 31) * 4;
        float4 v = make_float4(0.f, 0.f, 0.f, 0.f);
        if (rowBase + row < N_ROWS)
            v = *(const float4*)&X[(size_t)(rowBase + row) * D_IN + k4];
        const float xs[4] = {v.x, v.y, v.z, v.w};
        __nv_bfloat16 h[4], l[4], q[4];
        #pragma unroll
        for (int e = 0; e < 4; e++) {
            split2(xs[e], h[e], l[e]);
            q[e] = __float2bfloat16(xs[e] * xs[e]);
        }
        int o = row * P0B + k4 * 2;
        *(uint32_t*)(sm + S_XH  + o)     = pk(h[0], h[1]);
        *(uint32_t*)(sm + S_XH  + o + 4) = pk(h[2], h[3]);
        *(uint32_t*)(sm + S_XL  + o)     = pk(l[0], l[1]);
        *(uint32_t*)(sm + S_XL  + o + 4) = pk(l[2], l[3]);
        *(uint32_t*)(sm + S_X2H + o)     = pk(q[0], q[1]);
        *(uint32_t*)(sm + S_X2H + o + 4) = pk(q[2], q[3]);
    }

    float accM1[2][4][4], accV1[2][4][4];
    #pragma unroll
    for (int a = 0; a < 2; a++)
        #pragma unroll
        for (int b = 0; b < 4; b++)
            #pragma unroll
            for (int c = 0; c < 4; c++) { accM1[a][b][c] = 0.f; accV1[a][b][c] = 0.f; }

    for (int nc = 0; nc < 8; nc++) {
        // ---- issue W1[nc] (single buffer) ------------------------------------
        {
            int row = t >> 2, k16 = t & 3;
            size_t go = (size_t)row * R_DIM + nc * 32 + k16 * 8;
            uint32_t so = sb + S_W1 + row * P1B + k16 * 16;
            CP16(so,              (const char*)&g_w1mh[go]);
            CP16(so + W1_MAT,     (const char*)&g_w1ml[go]);
            CP16(so + 2 * W1_MAT, (const char*)&g_w1a1[go]);
            CP16(so + 3 * W1_MAT, (const char*)&g_w1vh[go]);
        }
        CP_COMMIT();
        // ---- issue W0[nc+1] into stage (nc+1)&1 ------------------------------
        if (nc < 7) {
            uint32_t base = sb + S_W0 + ((nc + 1) & 1) * W0_STAGE;
            #pragma unroll
            for (int it = 0; it < 2; it++) {
                int idx = t + it * 256;
                int r = idx >> 4, kk = idx & 15;
                size_t go = (size_t)((nc + 1) * 32 + r) * D_IN + kk * 8;
                uint32_t so = base + r * P0B + kk * 16;
                CP16(so,              (const char*)&g_w0mh[go]);
                CP16(so + W0_MAT,     (const char*)&g_w0ml[go]);
                CP16(so + 2 * W0_MAT, (const char*)&g_w0vh[go]);
            }
        }
        CP_COMMIT();

        CP_WAIT(2);                      // W0[nc] arrived
        __syncthreads();

        // ---- layer0 MMA for this 32-col chunk (M 3-term, V 1-term) -----------
        const uint32_t w0b = sb + S_W0 + (nc & 1) * W0_STAGE;
        float aM[2][2][4], aV[2][2][4];
        #pragma unroll
        for (int a = 0; a < 2; a++)
            #pragma unroll
            for (int b = 0; b < 2; b++)
                #pragma unroll
                for (int c = 0; c < 4; c++) { aM[a][b][c] = 0.f; aV[a][b][c] = 0.f; }

        #pragma unroll
        for (int ks = 0; ks < 8; ks++) {
            const int k = ks * 16;
            uint32_t Axh[2][4], Axl[2][4], A2h[2][4];
            #pragma unroll
            for (int rf = 0; rf < 2; rf++) {
                int ar = wm_ * 32 + rf * 16 + lr + (sel & 1) * 8;
                int ac = k + (sel >> 1) * 8;
                uint32_t off = (uint32_t)(ar * P0B + ac * 2);
                LDSM4(Axh[rf], sb + S_XH + off);
                LDSM4(Axl[rf], sb + S_XL + off);
                LDSM4(A2h[rf], sb + S_X2H + off);
            }
            uint32_t Bmh[4], Bml[4], Bvh[4];
            {
                int br = wn * 16 + lr + (sel >> 1) * 8;
                int bc = k + (sel & 1) * 8;
                uint32_t off = (uint32_t)(br * P0B + bc * 2);
                LDSM4(Bmh, w0b + off);
                LDSM4(Bml, w0b + W0_MAT + off);
                LDSM4(Bvh, w0b + 2 * W0_MAT + off);
            }
            #pragma unroll
            for (int rf = 0; rf < 2; rf++) {
                #pragma unroll
                for (int cq = 0; cq < 2; cq++) {
                    int o2 = cq * 2;
                    mma16816(aM[rf][cq], Axh[rf], &Bmh[o2]);
                    mma16816(aM[rf][cq], Axh[rf], &Bml[o2]);
                    mma16816(aM[rf][cq], Axl[rf], &Bmh[o2]);
                    mma16816(aV[rf][cq], A2h[rf], &Bvh[o2]);
                }
            }
        }

        // ---- gate + split into layer1 A buffers -------------------------------
        #pragma unroll
        for (int rf = 0; rf < 2; rf++) {
            #pragma unroll
            for (int cq = 0; cq < 2; cq++) {
                int klocal = wn * 16 + cq * 8 + 2 * (lane & 3);
                #pragma unroll
                for (int half = 0; half < 2; half++) {
                    int lrow = wm_ * 32 + rf * 16 + (lane >> 2) + half * 8;
                    float m0 = aM[rf][cq][half * 2 + 0];
                    float m1 = aM[rf][cq][half * 2 + 1];
                    float v0 = aV[rf][cq][half * 2 + 0];
                    float v1 = aV[rf][cq][half * 2 + 1];
                    bool g0 = m0 > 0.f, g1 = m1 > 0.f;
                    m0 = g0 ? m0 : 0.f;  v0 = g0 ? v0 : 0.f;
                    m1 = g1 ? m1 : 0.f;  v1 = g1 ? v1 : 0.f;
                    __nv_bfloat16 h0, l0, h1, l1;
                    split2(m0, h0, l0);
                    split2(m1, h1, l1);
                    int o = lrow * P1B + klocal * 2;
                    *(uint32_t*)(sm + S_L1MH + o) = pk(h0, h1);
                    *(uint32_t*)(sm + S_L1ML + o) = pk(l0, l1);
                    *(uint32_t*)(sm + S_L1VH + o) =
                        pk(__float2bfloat16(v0), __float2bfloat16(v1));
                    *(uint32_t*)(sm + S_L12H + o) =
                        pk(__float2bfloat16(m0 * m0), __float2bfloat16(m1 * m1));
                }
            }
        }

        CP_WAIT(1);                      // W1[nc] arrived (W0[nc+1] may still fly)
        __syncthreads();

        // ---- layer1 MMA accumulate (M 3-term, V 2-term) ------------------------
        #pragma unroll
        for (int ks = 0; ks < 2; ks++) {
            const int k = ks * 16;
            uint32_t Amh[2][4], Aml[2][4], Avh[2][4], A2m[2][4];
            #pragma unroll
            for (int rf = 0; rf < 2; rf++) {
                int ar = wm_ * 32 + rf * 16 + lr + (sel & 1) * 8;
                int ac = k + (sel >> 1) * 8;
                uint32_t off = (uint32_t)(ar * P1B + ac * 2);
                LDSM4(Amh[rf], sb + S_L1MH + off);
                LDSM4(Aml[rf], sb + S_L1ML + off);
                LDSM4(Avh[rf], sb + S_L1VH + off);
                LDSM4(A2m[rf], sb + S_L12H + off);
            }
            uint32_t Bm[2][4], Bl[2][4], Ba[2][4], Bv[2][4];
            #pragma unroll
            for (int p = 0; p < 2; p++) {
                int br = wn * 32 + p * 16 + lr + (sel >> 1) * 8;
                int bc = k + (sel & 1) * 8;
                uint32_t off = (uint32_t)(br * P1B + bc * 2);
                LDSM4(Bm[p], sb + S_W1 + off);
                LDSM4(Bl[p], sb + S_W1 + W1_MAT + off);
                LDSM4(Ba[p], sb + S_W1 + 2 * W1_MAT + off);
                LDSM4(Bv[p], sb + S_W1 + 3 * W1_MAT + off);
            }
            #pragma unroll
            for (int rf = 0; rf < 2; rf++) {
                #pragma unroll
                for (int p = 0; p < 2; p++) {
                    #pragma unroll
                    for (int cq = 0; cq < 2; cq++) {
                        int cf = p * 2 + cq, o2 = cq * 2;
                        mma16816(accM1[rf][cf], Amh[rf], &Bm[p][o2]);
                        mma16816(accM1[rf][cf], Amh[rf], &Bl[p][o2]);
                        mma16816(accM1[rf][cf], Aml[rf], &Bm[p][o2]);
                        mma16816(accV1[rf][cf], Avh[rf], &Ba[p][o2]);
                        mma16816(accV1[rf][cf], A2m[rf], &Bv[p][o2]);
                    }
                }
            }
        }
        __syncthreads();                 // W1 + L1A buffers free for next chunk
    }

    // ---- epilogue: inv-variance weighting into smem staging --------------------
    float* sInv  = (float*)(sm + S_SINV);
    float* sMinv = (float*)(sm + S_SMINV);
    #pragma unroll
    for (int rf = 0; rf < 2; rf++) {
        #pragma unroll
        for (int cf = 0; cf < 4; cf++) {
            int col = wn * 32 + cf * 8 + 2 * (lane & 3);
            #pragma unroll
            for (int half = 0; half < 2; half++) {
                int lrow = wm_ * 32 + rf * 16 + (lane >> 2) + half * 8;
                float m0 = accM1[rf][cf][half * 2 + 0];
                float m1 = accM1[rf][cf][half * 2 + 1];
                float V0 = fmaxf(accV1[rf][cf][half * 2 + 0], EPS);
                float V1 = fmaxf(accV1[rf][cf][half * 2 + 1], EPS);
                float i0 = 1.f / V0, i1 = 1.f / V1;
                sInv[lrow * 65 + col]      = i0;
                sInv[lrow * 65 + col + 1]  = i1;
                sMinv[lrow * 65 + col]     = m0 * i0;
                sMinv[lrow * 65 + col + 1] = m1 * i1;
            }
        }
    }
    __syncthreads();

    // ---- block-level segmented reduce over sorted uids -> atomics ---------------
    const int* uids = (const int*)(sm + S_UID);
    int col = t & 63, grp = t >> 6;            // 4 groups x 32 rows
    float aI = 0.f, aM = 0.f;
    int cur = -1;
    for (int r0 = 0; r0 < 32; r0++) {
        int row = grp * 32 + r0;
        int uid = uids[row];
        if (uid != cur) {
            if (cur >= 0) {
                atomicAdd(&g_sum_inv[cur * D_OUT + col], aI);
                atomicAdd(&g_sum_minv[cur * D_OUT + col], aM);
            }
            cur = uid; aI = 0.f; aM = 0.f;
        }
        if (uid >= 0) {
            aI += sInv[row * 65 + col];
            aM += sMinv[row * 65 + col];
        }
    }
    if (cur >= 0) {
        atomicAdd(&g_sum_inv[cur * D_OUT + col], aI);
        atomicAdd(&g_sum_minv[cur * D_OUT + col], aM);
    }
}

// ---------------- finalize ----------------------------------------------------
__global__ __launch_bounds__(256) void finalize_kernel(float* __restrict__ out) {
    int id = blockIdx.x * 256 + threadIdx.x;
    if (id < U_DIM * D_OUT) {
        float var = 1.f / (g_sum_inv[id] + EPS);
        out[id]                 = g_sum_minv[id] * var;
        out[U_DIM * D_OUT + id] = var;
    }
}

// ---------------- launch -------------------------------------------------------
extern "C" void kernel_launch(void* const* d_in, const int* in_sizes, int n_in,
                              void* d_out, int out_size) {
    const float* X     = (const float*)d_in[0];
    const int*   X_idx = (const int*)d_in[1];
    const float* Wmu0  = (const float*)d_in[2];
    const float* Wlv0  = (const float*)d_in[3];
    const float* Wmu1  = (const float*)d_in[4];
    const float* Wlv1  = (const float*)d_in[5];
    float* out = (float*)d_out;
    (void)in_sizes; (void)n_in; (void)out_size;

    cudaFuncSetAttribute(fused_kernel, cudaFuncAttributeMaxDynamicSharedMemorySize,
                         SMEM_SZ);

    const int nBlocks = (N_ROWS + BM - 1) / BM;

    prep_kernel<<<(U_DIM * D_OUT + 255) / 256, 256>>>(Wmu0, Wlv0, Wmu1, Wlv1);
    fused_kernel<<<nBlocks, 256, SMEM_SZ>>>(X, X_idx);
    finalize_kernel<<<(U_DIM * D_OUT + 255) / 256, 256>>>(out);
}